// round 16
// baseline (speedup 1.0000x reference)
#include <cuda_runtime.h>

// Problem constants
#define NG 2048   // G
#define NC 16     // C
#define NM 16     // m
// exp(x/gamma) = ex2(x * 100 * log2(e));  gamma*ln(s) = lg2(s) * gamma*ln2
#define KEXP 144.2695040889f
#define KLOG 0.00693147180560f

#define NITEM (NC * NG)           // 32768 (c,g) items
#define A1_BLK 296                // 148 slices x 2 parity halves
#define A1_SLICES 148
#define A1_SMEM (NG * 9 * 8)      // 2048 g * 9 padded u64 = 147456 B

typedef unsigned long long u64;

// Packed layouts: element [g*16 + j] = (val[b=2j], val[b=2j+1])
__device__ u64 g_Rt2[NG * 16];        // R (un-normalized; scale in g_max)
__device__ u64 g_Cv2[NC * NG * 16];   // Cv_pre
__device__ u64 g_Hs2[NG * 16];        // Hs_pre
__device__ int g_max[16][8];          // banked float-bit maxes (values >= 0)
// slots: iter i uses 3i (Cv), 3i+1 (Hs), 3i+2 (R); slot 15 stays 0 => scale 1.
// Zero-init at load; replay-idempotent (atomicMax of identical values) => NO reset.

// ---- f32x2 helpers (sm_103a packed fp32) ----
__device__ __forceinline__ u64 pk(float x, float y) {
    u64 v; asm("mov.b64 %0, {%1,%2};" : "=l"(v) : "f"(x), "f"(y)); return v;
}
__device__ __forceinline__ float2 unpk(u64 v) {
    float2 r; asm("mov.b64 {%0,%1}, %2;" : "=f"(r.x), "=f"(r.y) : "l"(v)); return r;
}
__device__ __forceinline__ u64 mul2(u64 a, u64 b) {
    u64 c; asm("mul.rn.f32x2 %0, %1, %2;" : "=l"(c) : "l"(a), "l"(b)); return c;
}
__device__ __forceinline__ u64 fma2(u64 a, u64 b, u64 c) {
    u64 d; asm("fma.rn.f32x2 %0, %1, %2, %3;" : "=l"(d) : "l"(a), "l"(b), "l"(c)); return d;
}
__device__ __forceinline__ float ex2(float x) {
    float y; asm("ex2.approx.ftz.f32 %0, %1;" : "=f"(y) : "f"(x)); return y;
}
__device__ __forceinline__ float lg2(float x) {
    float y; asm("lg2.approx.f32 %0, %1;" : "=f"(y) : "f"(x)); return y;
}

// ---------------------------------------------------------------------------
__device__ __forceinline__ float get_scale(int slot) {
    int v = g_max[slot][0];
    #pragma unroll
    for (int k = 1; k < 8; k++) v = max(v, g_max[slot][k]);
    float m = __int_as_float(v);
    return (m > 1.0f) ? __fdividef(1.0f, m) : 1.0f;
}

// warp->block max reduce, one atomicMax per block. All 256 threads must call.
__device__ __forceinline__ void block_max_atomic(float val, int slot) {
    int v = __float_as_int(val);   // valid ordering: all values non-negative
    #pragma unroll
    for (int o = 16; o > 0; o >>= 1) v = max(v, __shfl_xor_sync(0xffffffffu, v, o));
    __shared__ int s_red[8];
    if ((threadIdx.x & 31) == 0) s_red[threadIdx.x >> 5] = v;
    __syncthreads();
    if (threadIdx.x == 0) {
        int m = s_red[0];
        #pragma unroll
        for (int k = 1; k < 8; k++) m = max(m, s_red[k]);
        atomicMax(&g_max[slot][blockIdx.x & 7], m);
    }
}

// ---------------------------------------------------------------------------
// kA1F2: FUSED init + iteration-0 kA (s3 == 1 exactly). 296 blocks x 256.
// Block = (slice, parity p): stages its 8-j half (jj = 8p + j) of x into smem
// once (no h loop), side-writes its g_Rt2 slice, gathers its item range via
// LDS with a straight-line body (NO index arrays -> no local-memory spill).
__global__ void __launch_bounds__(256, 1)
kA1F2(const float* __restrict__ x, const int* __restrict__ I, int slotOut) {
    extern __shared__ u64 sRt[];                  // [g*9 + j], j in 0..7
    const int tid   = threadIdx.x;
    const int lane  = tid & 31;
    const int q     = lane & 7;                   // j within half
    const int qi    = lane >> 3;                  // which of 4 items in warp
    const int wid   = tid >> 5;
    const int p     = blockIdx.x & 1;             // parity half
    const int slice = blockIdx.x >> 1;            // 0..147

    // ---- stage this half: sRt[g*9+j] = (x[16p+2j][g], x[16p+2j+1][g]) ----
    #pragma unroll 1
    for (int v = tid; v < NG * 8; v += 256) {
        int j = v >> 11;                          // 0..7
        int g = v & (NG - 1);
        int b0 = 16 * p + 2 * j;
        sRt[g * 9 + j] = pk(x[b0 * NG + g], x[(b0 + 1) * NG + g]);
    }
    __syncthreads();

    // ---- side-write this block's slice of g_Rt2 (replaces k_init) ----
    {
        int g0 = (int)(((long long)slice * NG) / A1_SLICES);
        int g1 = (int)(((long long)(slice + 1) * NG) / A1_SLICES);
        #pragma unroll 1
        for (int v = g0 * 8 + tid; v < g1 * 8; v += 256) {
            int g = v >> 3, j = v & 7;
            g_Rt2[g * 16 + 8 * p + j] = sRt[g * 9 + j];
        }
    }

    // ---- gather + product + LSE for item range (global jj = 8p + q) ----
    const int i0 = (int)(((long long)slice * NITEM) / A1_SLICES);
    const int i1 = (int)(((long long)(slice + 1) * NITEM) / A1_SLICES);
    const u64 kexp2 = pk(KEXP, KEXP);
    float lmax = 0.0f;

    #pragma unroll 1
    for (int base = i0; base < i1; base += 32) {
        int item = base + wid * 4 + qi;
        if (item < i1) {
            const int4* ip = reinterpret_cast<const int4*>(I) + item * 6;
            int4 a0 = ip[0], a1 = ip[1], a2 = ip[2],
                 a3 = ip[3], a4 = ip[4], a5 = ip[5];
            #define GA(i) sRt[(i) * 9 + q]
            u64 b0 = mul2(mul2(GA(a0.x), GA(a0.y)), GA(a0.z));
            u64 b1 = mul2(mul2(GA(a0.w), GA(a1.x)), GA(a1.y));
            u64 b2 = mul2(mul2(GA(a1.z), GA(a1.w)), GA(a2.x));
            u64 b3 = mul2(mul2(GA(a2.y), GA(a2.z)), GA(a2.w));
            u64 b4 = mul2(mul2(GA(a3.x), GA(a3.y)), GA(a3.z));
            u64 b5 = mul2(mul2(GA(a3.w), GA(a4.x)), GA(a4.y));
            u64 b6 = mul2(mul2(GA(a4.z), GA(a4.w)), GA(a5.x));
            u64 b7 = mul2(mul2(GA(a5.y), GA(a5.z)), GA(a5.w));
            #undef GA
            float2 c0 = unpk(b0), c1 = unpk(b1), c2 = unpk(b2), c3 = unpk(b3);
            float2 c4 = unpk(b4), c5 = unpk(b5), c6 = unpk(b6), c7 = unpk(b7);
            float mxx = fmaxf(fmaxf(fmaxf(c0.x, c1.x), fmaxf(c2.x, c3.x)),
                              fmaxf(fmaxf(c4.x, c5.x), fmaxf(c6.x, c7.x)));
            float mxy = fmaxf(fmaxf(fmaxf(c0.y, c1.y), fmaxf(c2.y, c3.y)),
                              fmaxf(fmaxf(c4.y, c5.y), fmaxf(c6.y, c7.y)));
            u64 mneg = pk(-mxx * KEXP, -mxy * KEXP);
            float sx = 0.0f, sy = 0.0f;
            {
                float2 f;
                f = unpk(fma2(b0, kexp2, mneg)); sx += ex2(f.x); sy += ex2(f.y);
                f = unpk(fma2(b1, kexp2, mneg)); sx += ex2(f.x); sy += ex2(f.y);
                f = unpk(fma2(b2, kexp2, mneg)); sx += ex2(f.x); sy += ex2(f.y);
                f = unpk(fma2(b3, kexp2, mneg)); sx += ex2(f.x); sy += ex2(f.y);
                f = unpk(fma2(b4, kexp2, mneg)); sx += ex2(f.x); sy += ex2(f.y);
                f = unpk(fma2(b5, kexp2, mneg)); sx += ex2(f.x); sy += ex2(f.y);
                f = unpk(fma2(b6, kexp2, mneg)); sx += ex2(f.x); sy += ex2(f.y);
                f = unpk(fma2(b7, kexp2, mneg)); sx += ex2(f.x); sy += ex2(f.y);
            }
            float cvx = fmaf(lg2(sx), KLOG, mxx);     // s3 == 1 in iteration 0
            float cvy = fmaf(lg2(sy), KLOG, mxy);
            g_Cv2[item * 16 + 8 * p + q] = pk(cvx, cvy);
            lmax = fmaxf(lmax, fmaxf(cvx, cvy));
        }
    }
    block_max_atomic(lmax, slotOut);
}

// ---------------------------------------------------------------------------
// kA (iterations 1..4): FOUR (c,g) items per warp via ulonglong2 loads.
// grid 1024 x 256   [byte-identical to R13]
__global__ void __launch_bounds__(256, 3)
kA(const int* __restrict__ I, int slotR, int slotOut) {
    const int tid  = threadIdx.x;
    const int lane = tid & 31;
    const int q    = lane & 7;
    const int qi   = lane >> 3;
    const int item = (blockIdx.x * 8 + (tid >> 5)) * 4 + qi;

    float sR = get_scale(slotR);
    float s3 = sR * sR * sR;
    float kexp = s3 * KEXP;
    u64  kexp2 = pk(kexp, kexp);

    const int4* ip = reinterpret_cast<const int4*>(I) + item * 6;
    int4 a0 = ip[0], a1 = ip[1], a2 = ip[2], a3 = ip[3], a4 = ip[4], a5 = ip[5];
    int idx[24] = { a0.x,a0.y,a0.z,a0.w, a1.x,a1.y,a1.z,a1.w, a2.x,a2.y,a2.z,a2.w,
                    a3.x,a3.y,a3.z,a3.w, a4.x,a4.y,a4.z,a4.w, a5.x,a5.y,a5.z,a5.w };

    const ulonglong2* Rt = reinterpret_cast<const ulonglong2*>(g_Rt2);
    u64 b0[8], b1[8];
    #pragma unroll
    for (int s = 0; s < 8; s++) {
        ulonglong2 A = Rt[idx[3 * s + 0] * 8 + q];
        ulonglong2 Bv = Rt[idx[3 * s + 1] * 8 + q];
        ulonglong2 Cv = Rt[idx[3 * s + 2] * 8 + q];
        b0[s] = mul2(mul2(A.x, Bv.x), Cv.x);
        b1[s] = mul2(mul2(A.y, Bv.y), Cv.y);
    }

    float m0x, m0y, m1x, m1y;
    { float2 f0 = unpk(b0[0]), f1 = unpk(b1[0]); m0x = f0.x; m0y = f0.y; m1x = f1.x; m1y = f1.y; }
    #pragma unroll
    for (int s = 1; s < 8; s++) {
        float2 f0 = unpk(b0[s]), f1 = unpk(b1[s]);
        m0x = fmaxf(m0x, f0.x); m0y = fmaxf(m0y, f0.y);
        m1x = fmaxf(m1x, f1.x); m1y = fmaxf(m1y, f1.y);
    }
    u64 mneg0 = pk(-m0x * kexp, -m0y * kexp);
    u64 mneg1 = pk(-m1x * kexp, -m1y * kexp);
    float s0x = 0.0f, s0y = 0.0f, s1x = 0.0f, s1y = 0.0f;
    #pragma unroll
    for (int s = 0; s < 8; s++) {
        float2 f0 = unpk(fma2(b0[s], kexp2, mneg0));
        float2 f1 = unpk(fma2(b1[s], kexp2, mneg1));
        s0x += ex2(f0.x); s0y += ex2(f0.y);
        s1x += ex2(f1.x); s1y += ex2(f1.y);
    }
    float cv0x = fmaf(lg2(s0x), KLOG, m0x * s3);
    float cv0y = fmaf(lg2(s0y), KLOG, m0y * s3);
    float cv1x = fmaf(lg2(s1x), KLOG, m1x * s3);
    float cv1y = fmaf(lg2(s1y), KLOG, m1y * s3);

    ulonglong2 outv; outv.x = pk(cv0x, cv0y); outv.y = pk(cv1x, cv1y);
    reinterpret_cast<ulonglong2*>(g_Cv2)[item * 8 + q] = outv;

    block_max_atomic(fmaxf(fmaxf(cv0x, cv0y), fmaxf(cv1x, cv1y)), slotOut);
}

// ---------------------------------------------------------------------------
// kB: one g-pair per warp; softmax(W) computed per block; matvec + LSE_m.
// grid 128 x 256   [R14-validated]
__global__ void __launch_bounds__(256, 4)
kB(const float* __restrict__ W, int slotCv, int slotOut) {
    __shared__ u64 ws2[NM * NC];
    const int tid = threadIdx.x;
    if (tid < NM) {                               // softmax row tid (W tiny)
        float mx = -1e30f;
        #pragma unroll
        for (int cc = 0; cc < NC; cc++) mx = fmaxf(mx, W[tid * NC + cc]);
        float e[NC]; float sum = 0.0f;
        #pragma unroll
        for (int cc = 0; cc < NC; cc++) { e[cc] = ex2((W[tid * NC + cc] - mx) * 1.4426950409f); sum += e[cc]; }
        float inv = __fdividef(1.0f, sum);
        #pragma unroll
        for (int cc = 0; cc < NC; cc++) { float w = e[cc] * inv; ws2[tid * NC + cc] = pk(w, w); }
    }
    float s1 = get_scale(slotCv);
    __syncthreads();

    const int lane = tid & 31;
    const int hf   = lane >> 4;
    const int j    = lane & 15;
    const int g    = 2 * (blockIdx.x * 8 + (tid >> 5)) + hf;

    u64 h[NM];
    #pragma unroll
    for (int m = 0; m < NM; m++) h[m] = 0ull;
    #pragma unroll
    for (int cc = 0; cc < NC; cc++) {
        u64 cvc = g_Cv2[(cc * NG + g) * 16 + j];
        #pragma unroll
        for (int m = 0; m < NM; m++) h[m] = fma2(ws2[m * NC + cc], cvc, h[m]);
    }
    float2 hh[NM];
    #pragma unroll
    for (int m = 0; m < NM; m++) hh[m] = unpk(h[m]);
    float mxx = hh[0].x, mxy = hh[0].y;
    #pragma unroll
    for (int m = 1; m < NM; m++) { mxx = fmaxf(mxx, hh[m].x); mxy = fmaxf(mxy, hh[m].y); }
    float k1 = s1 * KEXP;
    u64 k12 = pk(k1, k1), mneg = pk(-mxx * k1, -mxy * k1);
    float sx = 0.0f, sy = 0.0f;
    #pragma unroll
    for (int m = 0; m < NM; m++) {
        float2 f = unpk(fma2(h[m], k12, mneg));
        sx += ex2(f.x); sy += ex2(f.y);
    }
    float hsx = fmaf(lg2(sx), KLOG, mxx * s1);
    float hsy = fmaf(lg2(sy), KLOG, mxy * s1);
    g_Hs2[g * 16 + j] = pk(hsx, hsy);
    block_max_atomic(fmaxf(hsx, hsy), slotOut);
}

// ---------------------------------------------------------------------------
// kC: elementwise 2-way softor merge, R in place.  grid 128 x 256
__global__ void __launch_bounds__(256, 4)
kC(int slotR, int slotHs, int slotOut) {
    int t = blockIdx.x * blockDim.x + threadIdx.x;
    float sR = get_scale(slotR);
    float s2 = get_scale(slotHs);

    float2 rr = unpk(g_Rt2[t]);
    float2 hv = unpk(g_Hs2[t]);
    float ax = rr.x * sR, ay = rr.y * sR;
    float bx = hv.x * s2, by = hv.y * s2;
    float mxx = fmaxf(ax, bx), mnx = fminf(ax, bx);
    float mxy = fmaxf(ay, by), mny = fminf(ay, by);
    float rx = fmaf(lg2(1.0f + ex2((mnx - mxx) * KEXP)), KLOG, mxx);
    float ry = fmaf(lg2(1.0f + ex2((mny - mxy) * KEXP)), KLOG, mxy);
    g_Rt2[t] = pk(rx, ry);
    block_max_atomic(fmaxf(rx, ry), slotOut);
}

// ---------------------------------------------------------------------------
// kOut: final scale + unpack back to (B, G).  grid 256 x 256
__global__ void kOut(float* __restrict__ out, int slotR) {
    int t = blockIdx.x * blockDim.x + threadIdx.x;   // t = b*NG + g
    float s = get_scale(slotR);
    int b = t >> 11, g = t & (NG - 1);
    float2 v = unpk(g_Rt2[g * 16 + (b >> 1)]);
    out[t] = ((b & 1) ? v.y : v.x) * s;
}

// ---------------------------------------------------------------------------
extern "C" void kernel_launch(void* const* d_in, const int* in_sizes, int n_in,
                              void* d_out, int out_size) {
    const float* x = (const float*)d_in[0];   // (32, 2048) f32
    const float* W = (const float*)d_in[1];   // (16, 16) f32
    const int*   I = (const int*)  d_in[2];   // (16, 2048, 8, 3) i32
    float* out = (float*)d_out;               // (32, 2048) f32

    cudaFuncSetAttribute(kA1F2, cudaFuncAttributeMaxDynamicSharedMemorySize, A1_SMEM);

    // iteration 0: fused init + kA (slots 0,1,2; slot 15 stays 0 => scale 1)
    kA1F2<<<A1_BLK, 256, A1_SMEM>>>(x, I, 0);
    kB   <<<128, 256>>>(W, 0, 1);
    kC   <<<128, 256>>>(15, 1, 2);
    // iterations 1..4
    for (int i = 1; i < 5; i++) {
        kA<<<1024, 256>>>(I, 3 * i - 1, 3 * i);
        kB<<<128,  256>>>(W, 3 * i, 3 * i + 1);
        kC<<<128,  256>>>(3 * i - 1, 3 * i + 1, 3 * i + 2);
    }
    kOut<<<256, 256>>>(out, 14);
}

// round 17
// speedup vs baseline: 1.2059x; 1.2059x over previous
#include <cuda_runtime.h>

// Problem constants
#define NG 2048   // G
#define NC 16     // C
#define NM 16     // m
// exp(x/gamma) = ex2(x * 100 * log2(e));  gamma*ln(s) = lg2(s) * gamma*ln2
#define KEXP 144.2695040889f
#define KLOG 0.00693147180560f

#define NITEM (NC * NG)        // 32768 (c,g) items
#define A0_SLICES 74           // item/g slices
#define A0_BLK (A0_SLICES * 8) // x 8 j-pair parities = 592 = 148 SMs x 4

typedef unsigned long long u64;

// Packed layouts: element [g*16 + j] = (val[b=2j], val[b=2j+1])
__device__ u64 g_Rt2[NG * 16];        // R (un-normalized; scale in g_max)
__device__ u64 g_Cv2[NC * NG * 16];   // Cv_pre
__device__ u64 g_Hs2[NG * 16];        // Hs_pre
__device__ int g_max[16][8];          // banked float-bit maxes (values >= 0)
// slots: iter i uses 3i (Cv), 3i+1 (Hs), 3i+2 (R); slot 15 stays 0 => scale 1.
// Zero-init at load; replay-idempotent (atomicMax of identical values) => NO reset.

// ---- f32x2 helpers (sm_103a packed fp32) ----
__device__ __forceinline__ u64 pk(float x, float y) {
    u64 v; asm("mov.b64 %0, {%1,%2};" : "=l"(v) : "f"(x), "f"(y)); return v;
}
__device__ __forceinline__ float2 unpk(u64 v) {
    float2 r; asm("mov.b64 {%0,%1}, %2;" : "=f"(r.x), "=f"(r.y) : "l"(v)); return r;
}
__device__ __forceinline__ u64 mul2(u64 a, u64 b) {
    u64 c; asm("mul.rn.f32x2 %0, %1, %2;" : "=l"(c) : "l"(a), "l"(b)); return c;
}
__device__ __forceinline__ u64 fma2(u64 a, u64 b, u64 c) {
    u64 d; asm("fma.rn.f32x2 %0, %1, %2, %3;" : "=l"(d) : "l"(a), "l"(b), "l"(c)); return d;
}
__device__ __forceinline__ float ex2(float x) {
    float y; asm("ex2.approx.ftz.f32 %0, %1;" : "=f"(y) : "f"(x)); return y;
}
__device__ __forceinline__ float lg2(float x) {
    float y; asm("lg2.approx.f32 %0, %1;" : "=f"(y) : "f"(x)); return y;
}

// ---------------------------------------------------------------------------
__device__ __forceinline__ float get_scale(int slot) {
    int v = g_max[slot][0];
    #pragma unroll
    for (int k = 1; k < 8; k++) v = max(v, g_max[slot][k]);
    float m = __int_as_float(v);
    return (m > 1.0f) ? __fdividef(1.0f, m) : 1.0f;
}

// warp->block max reduce, one atomicMax per block. All 256 threads must call.
__device__ __forceinline__ void block_max_atomic(float val, int slot) {
    int v = __float_as_int(val);   // valid ordering: all values non-negative
    #pragma unroll
    for (int o = 16; o > 0; o >>= 1) v = max(v, __shfl_xor_sync(0xffffffffu, v, o));
    __shared__ int s_red[8];
    if ((threadIdx.x & 31) == 0) s_red[threadIdx.x >> 5] = v;
    __syncthreads();
    if (threadIdx.x == 0) {
        int m = s_red[0];
        #pragma unroll
        for (int k = 1; k < 8; k++) m = max(m, s_red[k]);
        atomicMax(&g_max[slot][blockIdx.x & 7], m);
    }
}

// ---------------------------------------------------------------------------
// kA0F: FUSED init + iteration-0 kA (s3 == 1 exactly).
// 592 blocks x 256, 48KB STATIC smem -> 4 blocks/SM, one wave, 32 warps/SM.
// Block = (slice, parity p in 0..7): stages j-pair {2p, 2p+1} of x (4 b-rows,
// coalesced), side-writes its g_Rt2 slice, gathers its item range via LDS.64.
// 16 items per warp, 2 lanes (jq) per item; straight-line body, no idx array.
__global__ void __launch_bounds__(256, 4)
kA0F(const float* __restrict__ x, const int* __restrict__ I, int slotOut) {
    __shared__ u64 sRt[NG * 3];                   // [g*3 + jq]; 49152 B exactly
    const int tid   = threadIdx.x;
    const int lane  = tid & 31;
    const int jq    = lane & 1;                   // j within pair
    const int qi    = lane >> 1;                  // item 0..15 within warp
    const int wid   = tid >> 5;
    const int p     = blockIdx.x & 7;             // j-pair parity (jj = 2p+jq)
    const int slice = blockIdx.x >> 3;            // 0..73

    // ---- stage: sRt[g*3+jq] = (x[4p+2jq][g], x[4p+2jq+1][g]); coalesced ----
    #pragma unroll 1
    for (int v = tid; v < NG * 2; v += 256) {
        int j = v >> 11;                          // 0..1
        int g = v & (NG - 1);
        int b0 = 4 * p + 2 * j;
        sRt[g * 3 + j] = pk(x[b0 * NG + g], x[(b0 + 1) * NG + g]);
    }
    __syncthreads();

    // ---- side-write this block's (g-slice, jj-pair) of g_Rt2 ----
    {
        int g0 = (slice * NG) / A0_SLICES;
        int g1 = ((slice + 1) * NG) / A0_SLICES;
        #pragma unroll 1
        for (int v = tid; v < (g1 - g0) * 2; v += 256) {
            int g = g0 + (v >> 1), j = v & 1;
            g_Rt2[g * 16 + 2 * p + j] = sRt[g * 3 + j];
        }
    }

    // ---- gather + product + LSE for item range (this block's jj = 2p+jq) ----
    const int i0 = (int)(((long long)slice * NITEM) / A0_SLICES);
    const int i1 = (int)(((long long)(slice + 1) * NITEM) / A0_SLICES);
    const u64 kexp2 = pk(KEXP, KEXP);
    float lmax = 0.0f;

    #pragma unroll 1
    for (int base = i0; base < i1; base += 128) {
        int item = base + wid * 16 + qi;
        if (item < i1) {
            const int4* ip = reinterpret_cast<const int4*>(I) + item * 6;
            int4 a0 = ip[0], a1 = ip[1], a2 = ip[2],
                 a3 = ip[3], a4 = ip[4], a5 = ip[5];
            #define GA(i) sRt[(i) * 3 + jq]
            u64 b0 = mul2(mul2(GA(a0.x), GA(a0.y)), GA(a0.z));
            u64 b1 = mul2(mul2(GA(a0.w), GA(a1.x)), GA(a1.y));
            u64 b2 = mul2(mul2(GA(a1.z), GA(a1.w)), GA(a2.x));
            u64 b3 = mul2(mul2(GA(a2.y), GA(a2.z)), GA(a2.w));
            u64 b4 = mul2(mul2(GA(a3.x), GA(a3.y)), GA(a3.z));
            u64 b5 = mul2(mul2(GA(a3.w), GA(a4.x)), GA(a4.y));
            u64 b6 = mul2(mul2(GA(a4.z), GA(a4.w)), GA(a5.x));
            u64 b7 = mul2(mul2(GA(a5.y), GA(a5.z)), GA(a5.w));
            #undef GA
            float2 c0 = unpk(b0), c1 = unpk(b1), c2 = unpk(b2), c3 = unpk(b3);
            float2 c4 = unpk(b4), c5 = unpk(b5), c6 = unpk(b6), c7 = unpk(b7);
            float mxx = fmaxf(fmaxf(fmaxf(c0.x, c1.x), fmaxf(c2.x, c3.x)),
                              fmaxf(fmaxf(c4.x, c5.x), fmaxf(c6.x, c7.x)));
            float mxy = fmaxf(fmaxf(fmaxf(c0.y, c1.y), fmaxf(c2.y, c3.y)),
                              fmaxf(fmaxf(c4.y, c5.y), fmaxf(c6.y, c7.y)));
            u64 mneg = pk(-mxx * KEXP, -mxy * KEXP);
            float sx = 0.0f, sy = 0.0f;
            {
                float2 f;
                f = unpk(fma2(b0, kexp2, mneg)); sx += ex2(f.x); sy += ex2(f.y);
                f = unpk(fma2(b1, kexp2, mneg)); sx += ex2(f.x); sy += ex2(f.y);
                f = unpk(fma2(b2, kexp2, mneg)); sx += ex2(f.x); sy += ex2(f.y);
                f = unpk(fma2(b3, kexp2, mneg)); sx += ex2(f.x); sy += ex2(f.y);
                f = unpk(fma2(b4, kexp2, mneg)); sx += ex2(f.x); sy += ex2(f.y);
                f = unpk(fma2(b5, kexp2, mneg)); sx += ex2(f.x); sy += ex2(f.y);
                f = unpk(fma2(b6, kexp2, mneg)); sx += ex2(f.x); sy += ex2(f.y);
                f = unpk(fma2(b7, kexp2, mneg)); sx += ex2(f.x); sy += ex2(f.y);
            }
            float cvx = fmaf(lg2(sx), KLOG, mxx);     // s3 == 1 in iteration 0
            float cvy = fmaf(lg2(sy), KLOG, mxy);
            g_Cv2[item * 16 + 2 * p + jq] = pk(cvx, cvy);
            lmax = fmaxf(lmax, fmaxf(cvx, cvy));
        }
    }

    // ---- block max -> atomicMax; reduction scratch REUSES sRt (post-sync) ----
    __syncthreads();                              // all gathers done
    int v = __float_as_int(lmax);
    #pragma unroll
    for (int o = 16; o > 0; o >>= 1) v = max(v, __shfl_xor_sync(0xffffffffu, v, o));
    int* s_red = (int*)sRt;
    if (lane == 0) s_red[wid] = v;
    __syncthreads();
    if (tid == 0) {
        int m = s_red[0];
        #pragma unroll
        for (int k = 1; k < 8; k++) m = max(m, s_red[k]);
        atomicMax(&g_max[slotOut][blockIdx.x & 7], m);
    }
}

// ---------------------------------------------------------------------------
// kA (iterations 1..4): FOUR (c,g) items per warp via ulonglong2 loads.
// grid 1024 x 256   [byte-identical to R13]
__global__ void __launch_bounds__(256, 3)
kA(const int* __restrict__ I, int slotR, int slotOut) {
    const int tid  = threadIdx.x;
    const int lane = tid & 31;
    const int q    = lane & 7;
    const int qi   = lane >> 3;
    const int item = (blockIdx.x * 8 + (tid >> 5)) * 4 + qi;

    float sR = get_scale(slotR);
    float s3 = sR * sR * sR;
    float kexp = s3 * KEXP;
    u64  kexp2 = pk(kexp, kexp);

    const int4* ip = reinterpret_cast<const int4*>(I) + item * 6;
    int4 a0 = ip[0], a1 = ip[1], a2 = ip[2], a3 = ip[3], a4 = ip[4], a5 = ip[5];
    int idx[24] = { a0.x,a0.y,a0.z,a0.w, a1.x,a1.y,a1.z,a1.w, a2.x,a2.y,a2.z,a2.w,
                    a3.x,a3.y,a3.z,a3.w, a4.x,a4.y,a4.z,a4.w, a5.x,a5.y,a5.z,a5.w };

    const ulonglong2* Rt = reinterpret_cast<const ulonglong2*>(g_Rt2);
    u64 b0[8], b1[8];
    #pragma unroll
    for (int s = 0; s < 8; s++) {
        ulonglong2 A = Rt[idx[3 * s + 0] * 8 + q];
        ulonglong2 Bv = Rt[idx[3 * s + 1] * 8 + q];
        ulonglong2 Cv = Rt[idx[3 * s + 2] * 8 + q];
        b0[s] = mul2(mul2(A.x, Bv.x), Cv.x);
        b1[s] = mul2(mul2(A.y, Bv.y), Cv.y);
    }

    float m0x, m0y, m1x, m1y;
    { float2 f0 = unpk(b0[0]), f1 = unpk(b1[0]); m0x = f0.x; m0y = f0.y; m1x = f1.x; m1y = f1.y; }
    #pragma unroll
    for (int s = 1; s < 8; s++) {
        float2 f0 = unpk(b0[s]), f1 = unpk(b1[s]);
        m0x = fmaxf(m0x, f0.x); m0y = fmaxf(m0y, f0.y);
        m1x = fmaxf(m1x, f1.x); m1y = fmaxf(m1y, f1.y);
    }
    u64 mneg0 = pk(-m0x * kexp, -m0y * kexp);
    u64 mneg1 = pk(-m1x * kexp, -m1y * kexp);
    float s0x = 0.0f, s0y = 0.0f, s1x = 0.0f, s1y = 0.0f;
    #pragma unroll
    for (int s = 0; s < 8; s++) {
        float2 f0 = unpk(fma2(b0[s], kexp2, mneg0));
        float2 f1 = unpk(fma2(b1[s], kexp2, mneg1));
        s0x += ex2(f0.x); s0y += ex2(f0.y);
        s1x += ex2(f1.x); s1y += ex2(f1.y);
    }
    float cv0x = fmaf(lg2(s0x), KLOG, m0x * s3);
    float cv0y = fmaf(lg2(s0y), KLOG, m0y * s3);
    float cv1x = fmaf(lg2(s1x), KLOG, m1x * s3);
    float cv1y = fmaf(lg2(s1y), KLOG, m1y * s3);

    ulonglong2 outv; outv.x = pk(cv0x, cv0y); outv.y = pk(cv1x, cv1y);
    reinterpret_cast<ulonglong2*>(g_Cv2)[item * 8 + q] = outv;

    block_max_atomic(fmaxf(fmaxf(cv0x, cv0y), fmaxf(cv1x, cv1y)), slotOut);
}

// ---------------------------------------------------------------------------
// kB: one g-pair per warp; softmax(W) computed per block; matvec + LSE_m.
// grid 128 x 256   [R14/R15-validated]
__global__ void __launch_bounds__(256, 4)
kB(const float* __restrict__ W, int slotCv, int slotOut) {
    __shared__ u64 ws2[NM * NC];
    const int tid = threadIdx.x;
    if (tid < NM) {                               // softmax row tid (W tiny)
        float mx = -1e30f;
        #pragma unroll
        for (int cc = 0; cc < NC; cc++) mx = fmaxf(mx, W[tid * NC + cc]);
        float e[NC]; float sum = 0.0f;
        #pragma unroll
        for (int cc = 0; cc < NC; cc++) { e[cc] = ex2((W[tid * NC + cc] - mx) * 1.4426950409f); sum += e[cc]; }
        float inv = __fdividef(1.0f, sum);
        #pragma unroll
        for (int cc = 0; cc < NC; cc++) { float w = e[cc] * inv; ws2[tid * NC + cc] = pk(w, w); }
    }
    float s1 = get_scale(slotCv);
    __syncthreads();

    const int lane = tid & 31;
    const int hf   = lane >> 4;
    const int j    = lane & 15;
    const int g    = 2 * (blockIdx.x * 8 + (tid >> 5)) + hf;

    u64 h[NM];
    #pragma unroll
    for (int m = 0; m < NM; m++) h[m] = 0ull;
    #pragma unroll
    for (int cc = 0; cc < NC; cc++) {
        u64 cvc = g_Cv2[(cc * NG + g) * 16 + j];
        #pragma unroll
        for (int m = 0; m < NM; m++) h[m] = fma2(ws2[m * NC + cc], cvc, h[m]);
    }
    float2 hh[NM];
    #pragma unroll
    for (int m = 0; m < NM; m++) hh[m] = unpk(h[m]);
    float mxx = hh[0].x, mxy = hh[0].y;
    #pragma unroll
    for (int m = 1; m < NM; m++) { mxx = fmaxf(mxx, hh[m].x); mxy = fmaxf(mxy, hh[m].y); }
    float k1 = s1 * KEXP;
    u64 k12 = pk(k1, k1), mneg = pk(-mxx * k1, -mxy * k1);
    float sx = 0.0f, sy = 0.0f;
    #pragma unroll
    for (int m = 0; m < NM; m++) {
        float2 f = unpk(fma2(h[m], k12, mneg));
        sx += ex2(f.x); sy += ex2(f.y);
    }
    float hsx = fmaf(lg2(sx), KLOG, mxx * s1);
    float hsy = fmaf(lg2(sy), KLOG, mxy * s1);
    g_Hs2[g * 16 + j] = pk(hsx, hsy);
    block_max_atomic(fmaxf(hsx, hsy), slotOut);
}

// ---------------------------------------------------------------------------
// kC: elementwise 2-way softor merge, R in place.  grid 128 x 256
__global__ void __launch_bounds__(256, 4)
kC(int slotR, int slotHs, int slotOut) {
    int t = blockIdx.x * blockDim.x + threadIdx.x;
    float sR = get_scale(slotR);
    float s2 = get_scale(slotHs);

    float2 rr = unpk(g_Rt2[t]);
    float2 hv = unpk(g_Hs2[t]);
    float ax = rr.x * sR, ay = rr.y * sR;
    float bx = hv.x * s2, by = hv.y * s2;
    float mxx = fmaxf(ax, bx), mnx = fminf(ax, bx);
    float mxy = fmaxf(ay, by), mny = fminf(ay, by);
    float rx = fmaf(lg2(1.0f + ex2((mnx - mxx) * KEXP)), KLOG, mxx);
    float ry = fmaf(lg2(1.0f + ex2((mny - mxy) * KEXP)), KLOG, mxy);
    g_Rt2[t] = pk(rx, ry);
    block_max_atomic(fmaxf(rx, ry), slotOut);
}

// ---------------------------------------------------------------------------
// kOut: final scale + unpack back to (B, G).  grid 256 x 256
__global__ void kOut(float* __restrict__ out, int slotR) {
    int t = blockIdx.x * blockDim.x + threadIdx.x;   // t = b*NG + g
    float s = get_scale(slotR);
    int b = t >> 11, g = t & (NG - 1);
    float2 v = unpk(g_Rt2[g * 16 + (b >> 1)]);
    out[t] = ((b & 1) ? v.y : v.x) * s;
}

// ---------------------------------------------------------------------------
extern "C" void kernel_launch(void* const* d_in, const int* in_sizes, int n_in,
                              void* d_out, int out_size) {
    const float* x = (const float*)d_in[0];   // (32, 2048) f32
    const float* W = (const float*)d_in[1];   // (16, 16) f32
    const int*   I = (const int*)  d_in[2];   // (16, 2048, 8, 3) i32
    float* out = (float*)d_out;               // (32, 2048) f32

    // iteration 0: fused init + kA (slots 0,1,2; slot 15 stays 0 => scale 1)
    kA0F<<<A0_BLK, 256>>>(x, I, 0);
    kB  <<<128, 256>>>(W, 0, 1);
    kC  <<<128, 256>>>(15, 1, 2);
    // iterations 1..4
    for (int i = 1; i < 5; i++) {
        kA<<<1024, 256>>>(I, 3 * i - 1, 3 * i);
        kB<<<128,  256>>>(W, 3 * i, 3 * i + 1);
        kC<<<128,  256>>>(3 * i - 1, 3 * i + 1, 3 * i + 2);
    }
    kOut<<<256, 256>>>(out, 14);
}